// round 3
// baseline (speedup 1.0000x reference)
#include <cuda_runtime.h>
#include <cuda_bf16.h>

// Rejection sampler for speculative decoding.
// Inputs indexed from the END of d_in (robust to whether the scalar
// num_draft_tokens input is materialized by the harness):
//   d_in[0]        draft_token_ids  int32 [N]
//   d_in[n_in-5]   draft_probs      f32   [N,V]
//   d_in[n_in-4]   target_probs     f32   [N,V]
//   d_in[n_in-3]   bonus_token_ids  int32 [B,1]
//   d_in[n_in-2]   uniform_samples  f32   [N]
//   d_in[n_in-1]   uniform_recover  f32   [N]
// Output buffer is FLOAT32 (harness flattens the reference tuple):
//   out[B,K+1], num_accepted[B], accepted[B], recovered[B], bonus[B].

#define EPS 1e-10f
#define THREADS 512
#define NWARP (THREADS / 32)

// Per-row scratch (N <= 8192 supported; actual N = 1024).
__device__ int g_accept[8192];
__device__ int g_rec[8192];

// One CTA per row. Phase 1: stream t/d once from HBM, compute adj = max(t-d,0)
// into dynamic SMEM (V floats). Phase 2: blocked scan + inverse-CDF count,
// all from SMEM. Also performs the scalar acceptance test for the row.
__global__ void __launch_bounds__(THREADS, 1)
row_kernel(const int* __restrict__ tok,
           const float* __restrict__ dp,
           const float* __restrict__ tp,
           const float* __restrict__ u_samp,
           const float* __restrict__ u_rec,
           int V)
{
    extern __shared__ float s_adj[];           // V floats
    __shared__ float s_warp_inc[NWARP];
    __shared__ float s_warp_excl[NWARP];
    __shared__ float s_total;
    __shared__ int   s_count;

    const int row = blockIdx.x;
    const int tid = threadIdx.x;
    const int lane = tid & 31;
    const int wid  = tid >> 5;

    const float* __restrict__ d = dp + (size_t)row * V;
    const float* __restrict__ t = tp + (size_t)row * V;

    // ---- Phase 1: global -> SMEM, adj = max(t - d, 0), fully coalesced float4
    const int V4 = V >> 2;
    const float4* __restrict__ d4 = (const float4*)d;
    const float4* __restrict__ t4 = (const float4*)t;
    float4* s4 = (float4*)s_adj;
    for (int j = tid; j < V4; j += THREADS) {
        float4 a = t4[j];
        float4 b = d4[j];
        float4 r;
        r.x = fmaxf(a.x - b.x, 0.0f);
        r.y = fmaxf(a.y - b.y, 0.0f);
        r.z = fmaxf(a.z - b.z, 0.0f);
        r.w = fmaxf(a.w - b.w, 0.0f);
        s4[j] = r;
    }
    for (int j = (V4 << 2) + tid; j < V; j += THREADS)
        s_adj[j] = fmaxf(t[j] - d[j], 0.0f);

    if (tid == 0) s_count = 0;
    __syncthreads();

    // ---- Phase 2a: contiguous per-thread chunk sums (sequential order)
    const int C   = (V + THREADS - 1) / THREADS;
    const int beg = tid * C;
    float cs = 0.0f;
    #pragma unroll 4
    for (int i = 0; i < C; i++) {
        int j = beg + i;
        if (j < V) cs += s_adj[j];
    }

    // ---- Block exclusive scan of chunk sums
    float v = cs;  // inclusive within warp
    #pragma unroll
    for (int o = 1; o < 32; o <<= 1) {
        float n = __shfl_up_sync(0xFFFFFFFFu, v, o);
        if (lane >= o) v += n;
    }
    if (lane == 31) s_warp_inc[wid] = v;
    __syncthreads();
    if (tid == 0) {
        float acc = 0.0f;
        #pragma unroll
        for (int w = 0; w < NWARP; w++) {
            s_warp_excl[w] = acc;
            acc += s_warp_inc[w];
        }
        s_total = acc;
    }
    __syncthreads();
    const float s      = s_total;
    float       excl   = s_warp_excl[wid] + (v - cs);  // exclusive prefix of my chunk

    // ---- Phase 2b: inverse-CDF count
    int cnt = 0;
    if (s > EPS) {
        const float T = u_rec[row] * s;   // cumsum(adj)/s < u  <=>  cumsum(adj) < u*s
        float run = excl;
        #pragma unroll 4
        for (int i = 0; i < C; i++) {
            int j = beg + i;
            if (j < V) {
                run += s_adj[j];
                cnt += (run < T) ? 1 : 0;
            }
        }
    } else {
        // Fallback (residual mass ~0): sample directly from target_probs.
        __syncthreads();
        for (int j = tid; j < V4; j += THREADS)
            s4[j] = t4[j];
        for (int j = (V4 << 2) + tid; j < V; j += THREADS)
            s_adj[j] = t[j];
        __syncthreads();
        float cs2 = 0.0f;
        for (int i = 0; i < C; i++) {
            int j = beg + i;
            if (j < V) cs2 += s_adj[j];
        }
        float v2 = cs2;
        #pragma unroll
        for (int o = 1; o < 32; o <<= 1) {
            float n = __shfl_up_sync(0xFFFFFFFFu, v2, o);
            if (lane >= o) v2 += n;
        }
        if (lane == 31) s_warp_inc[wid] = v2;
        __syncthreads();
        if (tid == 0) {
            float acc = 0.0f;
            #pragma unroll
            for (int w = 0; w < NWARP; w++) {
                s_warp_excl[w] = acc;
                acc += s_warp_inc[w];
            }
        }
        __syncthreads();
        float excl2 = s_warp_excl[wid] + (v2 - cs2);
        const float T = u_rec[row];
        float run = excl2;
        for (int i = 0; i < C; i++) {
            int j = beg + i;
            if (j < V) {
                run += s_adj[j];
                cnt += (run < T) ? 1 : 0;
            }
        }
    }

    // Warp-reduce counts, then block combine.
    #pragma unroll
    for (int o = 16; o > 0; o >>= 1)
        cnt += __shfl_down_sync(0xFFFFFFFFu, cnt, o);
    if (lane == 0) atomicAdd(&s_count, cnt);
    __syncthreads();

    if (tid == 0) {
        int rec = min(s_count, V - 1);
        g_rec[row] = rec;

        int tk = tok[row];
        float pd = d[tk];
        float pt = t[tk];
        float ratio = pt / fmaxf(pd, EPS);
        g_accept[row] = (u_samp[row] < fminf(1.0f, ratio)) ? 1 : 0;
    }
}

// Writes FLOAT32 outputs (token ids / counts are exactly representable).
__global__ void finalize_kernel(const int* __restrict__ tok,
                                const int* __restrict__ bonus,
                                float* __restrict__ out,
                                int B, int K, int out_size)
{
    int b = blockIdx.x * blockDim.x + threadIdx.x;
    if (b >= B) return;

    int n_acc = 0;
    for (int i = 0; i < K; i++) {
        if (g_accept[b * K + i]) n_acc++;
        else break;
    }
    bool all_acc = (n_acc == K);
    int rec_at = g_rec[b * K + min(n_acc, K - 1)];
    int fin = all_acc ? bonus[b] : rec_at;

    float* o = out + b * (K + 1);
    for (int i = 0; i <= K; i++)
        o[i] = (i < n_acc) ? (float)tok[b * K + i] : -1.0f;
    o[n_acc] = (float)fin;

    int base = B * (K + 1);
    if (base + 4 * B <= out_size) {
        out[base + b]         = (float)(n_acc + 1);      // num_accepted
        out[base + B + b]     = (float)n_acc;            // accepted_counts
        out[base + 2 * B + b] = all_acc ? 0.0f : 1.0f;   // recovered_counts
        out[base + 3 * B + b] = all_acc ? 1.0f : 0.0f;   // bonus_counts
    }
}

extern "C" void kernel_launch(void* const* d_in, const int* in_sizes, int n_in,
                              void* d_out, int out_size)
{
    // Index from the END: robust to presence/absence of the scalar input.
    const int*   tok   = (const int*)d_in[0];
    const float* dp    = (const float*)d_in[n_in - 5];
    const float* tp    = (const float*)d_in[n_in - 4];
    const int*   bonus = (const int*)d_in[n_in - 3];
    const float* us    = (const float*)d_in[n_in - 2];
    const float* ur    = (const float*)d_in[n_in - 1];
    float*       out   = (float*)d_out;

    const int N = in_sizes[0];
    const int B = in_sizes[n_in - 3];
    const int V = in_sizes[n_in - 4] / N;
    const int K = N / B;

    size_t smem = (size_t)V * sizeof(float);
    cudaFuncSetAttribute(row_kernel,
                         cudaFuncAttributeMaxDynamicSharedMemorySize,
                         (int)smem);

    row_kernel<<<N, THREADS, smem>>>(tok, dp, tp, us, ur, V);
    finalize_kernel<<<(B + 127) / 128, 128>>>(tok, bonus, out, B, K, out_size);
}

// round 5
// speedup vs baseline: 1.5407x; 1.5407x over previous
#include <cuda_runtime.h>
#include <cuda_bf16.h>

// Rejection sampler for speculative decoding — single fused kernel.
//
// Inputs indexed from the END of d_in (robust to the scalar input):
//   d_in[0]        draft_token_ids  int32 [N]
//   d_in[n_in-5]   draft_probs      f32   [N,V]
//   d_in[n_in-4]   target_probs     f32   [N,V]
//   d_in[n_in-3]   bonus_token_ids  int32 [B,1]
//   d_in[n_in-2]   uniform_samples  f32   [N]
//   d_in[n_in-1]   uniform_recover  f32   [N]
// Output FLOAT32: out[B,K+1], num_accepted[B], accepted[B], recovered[B], bonus[B].
//
// Strategy: one CTA per row. Phase 1 streams both prob rows once (coalesced
// float4), folding them into 250 per-128-element segment sums (adj and t) in
// ~2 KB SMEM — no V-sized stash. Phase 2 (warp 0) scans the 250 segment sums,
// locates the crossing segment of the monotone CDF, and re-reads only that one
// 512 B segment (L2-hot) to resolve the exact index. The last CTA to finish
// performs the B-row finalize, eliminating the separate kernel.

#define EPS 1e-10f
#define THREADS 512
#define NWARP (THREADS / 32)
#define SPL 8          // segments per lane in the phase-2 scan (supports V <= 32768)
#define MAXSEG 256

__device__ int g_accept[8192];
__device__ int g_rec[8192];
__device__ int g_done = 0;

__global__ void __launch_bounds__(THREADS)
fused_kernel(const int* __restrict__ tok,
             const float* __restrict__ dp,
             const float* __restrict__ tp,
             const int* __restrict__ bonus,
             const float* __restrict__ u_samp,
             const float* __restrict__ u_rec,
             float* __restrict__ out,
             int V, int B, int K, int out_size)
{
    __shared__ float s_seg_adj[MAXSEG];
    __shared__ float s_seg_t[MAXSEG];
    __shared__ int   s_last;

    const int row  = blockIdx.x;
    const int tid  = threadIdx.x;
    const int lane = tid & 31;
    const int wid  = tid >> 5;

    const float* __restrict__ d = dp + (size_t)row * V;
    const float* __restrict__ t = tp + (size_t)row * V;

    const int V4     = V >> 2;
    const int n_segs = (V + 127) >> 7;           // 128 elements per segment
    const int n_iter = (V4 + THREADS - 1) / THREADS;

    const float4* __restrict__ d4 = (const float4*)d;
    const float4* __restrict__ t4 = (const float4*)t;

    // ---- Phase 1: stream once, fold into segment sums (adj and t).
    for (int i = 0; i < n_iter; i++) {
        int j = i * THREADS + tid;               // float4 index
        float4 a = make_float4(0.f, 0.f, 0.f, 0.f);
        float4 b = a;
        if (j < V4) { a = t4[j]; b = d4[j]; }
        float av = fmaxf(a.x - b.x, 0.f) + fmaxf(a.y - b.y, 0.f)
                 + fmaxf(a.z - b.z, 0.f) + fmaxf(a.w - b.w, 0.f);
        float tv = a.x + a.y + a.z + a.w;
        #pragma unroll
        for (int o = 16; o > 0; o >>= 1) {
            av += __shfl_down_sync(0xFFFFFFFFu, av, o);
            tv += __shfl_down_sync(0xFFFFFFFFu, tv, o);
        }
        if (lane == 0) {
            int seg = i * NWARP + wid;           // warp covers 32 float4 = 128 elems
            if (seg < n_segs) { s_seg_adj[seg] = av; s_seg_t[seg] = tv; }
        }
    }
    __syncthreads();
    if (tid == 0 && (V & 3)) {                   // scalar tail (unused for V=32000)
        for (int e = V4 << 2; e < V; e++) {
            float tv = t[e], dv = d[e];
            s_seg_adj[e >> 7] += fmaxf(tv - dv, 0.f);
            s_seg_t[e >> 7]   += tv;
        }
    }
    __syncthreads();

    // ---- Acceptance test (warp 1, parallel with warp 0's phase 2).
    if (tid == 32) {
        int tk = tok[row];
        float pd = d[tk];
        float pt = t[tk];
        g_accept[row] = (u_samp[row] < fminf(1.f, pt / fmaxf(pd, EPS))) ? 1 : 0;
    }

    // ---- Phase 2 (warp 0): scan segment sums, find CDF crossing, resolve.
    if (wid == 0) {
        const float u = u_rec[row];

        float loc[SPL];
        float lsum, excl, stot;
        // scan adj segments
        {
            lsum = 0.f;
            #pragma unroll
            for (int k = 0; k < SPL; k++) {
                int sg = lane * SPL + k;
                float v = (sg < n_segs) ? s_seg_adj[sg] : 0.f;
                lsum += v; loc[k] = lsum;
            }
            float inc = lsum;
            #pragma unroll
            for (int o = 1; o < 32; o <<= 1) {
                float nb = __shfl_up_sync(0xFFFFFFFFu, inc, o);
                if (lane >= o) inc += nb;
            }
            excl = inc - lsum;
            stot = __shfl_sync(0xFFFFFFFFu, inc, 31);
        }

        const bool fb = !(stot > EPS);           // fallback: sample from target
        float T;
        if (fb) {
            // rebuild scan from t segment sums
            lsum = 0.f;
            #pragma unroll
            for (int k = 0; k < SPL; k++) {
                int sg = lane * SPL + k;
                float v = (sg < n_segs) ? s_seg_t[sg] : 0.f;
                lsum += v; loc[k] = lsum;
            }
            float inc = lsum;
            #pragma unroll
            for (int o = 1; o < 32; o <<= 1) {
                float nb = __shfl_up_sync(0xFFFFFFFFu, inc, o);
                if (lane >= o) inc += nb;
            }
            excl = inc - lsum;
            T = u;                               // target_probs already normalized
        } else {
            T = u * stot;                        // cumsum(adj)/s < u  <=>  cumsum < u*s
        }

        // first segment whose inclusive prefix reaches T
        int   local = SPL;
        float pbl   = 0.f;
        #pragma unroll
        for (int k = SPL - 1; k >= 0; k--) {
            if (excl + loc[k] >= T) { local = k; pbl = excl + (k > 0 ? loc[k - 1] : 0.f); }
        }
        int   cand = (local < SPL && lane * SPL + local < n_segs)
                   ? lane * SPL + local : 0x7FFFFFFF;
        float pb = pbl;
        #pragma unroll
        for (int o = 16; o > 0; o >>= 1) {
            int   oc  = __shfl_down_sync(0xFFFFFFFFu, cand, o);
            float opb = __shfl_down_sync(0xFFFFFFFFu, pb, o);
            if (oc < cand) { cand = oc; pb = opb; }
        }
        cand = __shfl_sync(0xFFFFFFFFu, cand, 0);
        pb   = __shfl_sync(0xFFFFFFFFu, pb, 0);

        int count;
        if (cand == 0x7FFFFFFF) {
            count = V;
        } else {
            // re-read the single crossing segment (512 B, L2-hot)
            int base = cand * 128 + lane * 4;
            float e0 = 0.f, e1 = 0.f, e2 = 0.f, e3 = 0.f;
            if (fb) {
                if (base + 0 < V) e0 = t[base + 0];
                if (base + 1 < V) e1 = t[base + 1];
                if (base + 2 < V) e2 = t[base + 2];
                if (base + 3 < V) e3 = t[base + 3];
            } else {
                if (base + 0 < V) e0 = fmaxf(t[base + 0] - d[base + 0], 0.f);
                if (base + 1 < V) e1 = fmaxf(t[base + 1] - d[base + 1], 0.f);
                if (base + 2 < V) e2 = fmaxf(t[base + 2] - d[base + 2], 0.f);
                if (base + 3 < V) e3 = fmaxf(t[base + 3] - d[base + 3], 0.f);
            }
            float p0 = e0, p1 = p0 + e1, p2 = p1 + e2, p3 = p2 + e3;
            float ls = p3;
            float inc = ls;
            #pragma unroll
            for (int o = 1; o < 32; o <<= 1) {
                float nb = __shfl_up_sync(0xFFFFFFFFu, inc, o);
                if (lane >= o) inc += nb;
            }
            float bofs = pb + (inc - ls);
            int c = 0;
            c += (base + 0 < V && bofs + p0 < T) ? 1 : 0;
            c += (base + 1 < V && bofs + p1 < T) ? 1 : 0;
            c += (base + 2 < V && bofs + p2 < T) ? 1 : 0;
            c += (base + 3 < V && bofs + p3 < T) ? 1 : 0;
            #pragma unroll
            for (int o = 16; o > 0; o >>= 1)
                c += __shfl_down_sync(0xFFFFFFFFu, c, o);
            count = cand * 128 + c;
        }
        if (lane == 0) g_rec[row] = min(count, V - 1);
    }

    // ---- Last-CTA finalize (replaces the separate kernel).
    __syncthreads();
    if (tid == 0) {
        __threadfence();                         // publish g_rec / g_accept
        int ticket = atomicAdd(&g_done, 1);
        s_last = (ticket == (int)gridDim.x - 1) ? 1 : 0;
        if (s_last) {
            g_done = 0;                          // reset for graph replay
            __threadfence();                     // order subsequent reads
        }
    }
    __syncthreads();
    if (s_last) {
        for (int b = tid; b < B; b += THREADS) {
            int n_acc = 0;
            for (int i = 0; i < K; i++) {
                if (g_accept[b * K + i]) n_acc++;
                else break;
            }
            bool all_acc = (n_acc == K);
            int rec_at = g_rec[b * K + min(n_acc, K - 1)];
            int fin = all_acc ? bonus[b] : rec_at;

            float* o = out + b * (K + 1);
            for (int i = 0; i <= K; i++)
                o[i] = (i < n_acc) ? (float)tok[b * K + i] : -1.0f;
            o[n_acc] = (float)fin;

            int base = B * (K + 1);
            if (base + 4 * B <= out_size) {
                out[base + b]         = (float)(n_acc + 1);
                out[base + B + b]     = (float)n_acc;
                out[base + 2 * B + b] = all_acc ? 0.0f : 1.0f;
                out[base + 3 * B + b] = all_acc ? 1.0f : 0.0f;
            }
        }
    }
}

extern "C" void kernel_launch(void* const* d_in, const int* in_sizes, int n_in,
                              void* d_out, int out_size)
{
    const int*   tok   = (const int*)d_in[0];
    const float* dp    = (const float*)d_in[n_in - 5];
    const float* tp    = (const float*)d_in[n_in - 4];
    const int*   bonus = (const int*)d_in[n_in - 3];
    const float* us    = (const float*)d_in[n_in - 2];
    const float* ur    = (const float*)d_in[n_in - 1];
    float*       out   = (float*)d_out;

    const int N = in_sizes[0];
    const int B = in_sizes[n_in - 3];
    const int V = in_sizes[n_in - 4] / N;
    const int K = N / B;

    fused_kernel<<<N, THREADS>>>(tok, dp, tp, bonus, us, ur, out,
                                 V, B, K, out_size);
}